// round 2
// baseline (speedup 1.0000x reference)
#include <cuda_runtime.h>
#include <math.h>
#include <stdint.h>

// Problem constants
#define SQ   256      // S
#define BB   64       // B
#define EE   300      // E
#define NH2  256      // H2
#define NH   512      // H
#define NT   10       // T
#define GC   1024     // 4*H2
#define MROWS 16384   // S*B
#define START_TAG 8
#define STOP_TAG  9

// ---------------- device scratch (no allocations allowed) ----------------
__device__ float g_Xp[2ull * 16384ull * 1024ull];   // input projections (bias folded), per dir
__device__ float g_hs[16384ull * 512ull];           // lstm_out (S,B,H) flat
__device__ float g_hbuf[2 * 2 * 64 * 256];          // h double buffer [parity][dir][b][k]
__device__ float g_feats[16384 * 10];               // (B,S,T) with row = b*S+s
__device__ unsigned char g_bps[256 * 64 * 10];      // backpointers
__device__ unsigned g_count = 0;                    // grid barrier count
__device__ unsigned g_phase = 0;                    // grid barrier phase (monotonic)

// =========================================================================
// Kernel 1: embedding gather + input projection GEMM (both directions)
//   Xp[dir][r][g] = emb[sent[r]] . wih_dir[g] + bih_dir[g] + bhh_dir[g]
//   r = s*B + b  (matches torch-style view (B,S,E)->(S,B,E))
// =========================================================================
#define BM 128
#define BN 64
#define BK 16

__global__ void __launch_bounds__(256) proj_gemm(
    const int* __restrict__ sent, const float* __restrict__ emb,
    const float* __restrict__ wih_f, const float* __restrict__ wih_b,
    const float* __restrict__ bih_f, const float* __restrict__ bhh_f,
    const float* __restrict__ bih_b, const float* __restrict__ bhh_b)
{
    __shared__ float As[BK][BM + 4];
    __shared__ float Bs[BK][BN + 4];

    const int tid   = threadIdx.x;
    const int m0    = blockIdx.y * BM;
    const int ng0   = blockIdx.x * BN;
    const int dir   = (ng0 >= GC) ? 1 : 0;
    const int n0    = ng0 - dir * GC;
    const float* __restrict__ W = dir ? wih_b : wih_f;

    const int rbase = tid >> 4;   // 0..15
    const int kloc  = tid & 15;   // 0..15

    int toks[8];
#pragma unroll
    for (int i = 0; i < 8; i++) toks[i] = sent[m0 + rbase + 16 * i];

    float acc[8][4];
#pragma unroll
    for (int i = 0; i < 8; i++)
#pragma unroll
        for (int j = 0; j < 4; j++) acc[i][j] = 0.f;

    const int tx = tid & 15;   // -> 4 cols
    const int ty = tid >> 4;   // -> 8 rows

    for (int k0 = 0; k0 < EE; k0 += BK) {
        const int  gk  = k0 + kloc;
        const bool kin = (gk < EE);
#pragma unroll
        for (int i = 0; i < 8; i++) {
            float v = kin ? emb[(size_t)toks[i] * EE + gk] : 0.f;
            As[kloc][rbase + 16 * i] = v;
        }
#pragma unroll
        for (int i = 0; i < 4; i++) {
            int n = rbase + 16 * i;
            Bs[kloc][n] = kin ? W[(size_t)(n0 + n) * EE + gk] : 0.f;
        }
        __syncthreads();
#pragma unroll
        for (int k = 0; k < BK; k++) {
            const float4* a4 = (const float4*)&As[k][0];
            const float4* b4 = (const float4*)&Bs[k][0];
            float4 A0 = a4[ty * 2], A1 = a4[ty * 2 + 1];
            float4 Bv = b4[tx];
            float av[8] = {A0.x, A0.y, A0.z, A0.w, A1.x, A1.y, A1.z, A1.w};
            float bv[4] = {Bv.x, Bv.y, Bv.z, Bv.w};
#pragma unroll
            for (int i = 0; i < 8; i++)
#pragma unroll
                for (int j = 0; j < 4; j++) acc[i][j] += av[i] * bv[j];
        }
        __syncthreads();
    }

    const float* bi = dir ? bih_b : bih_f;
    const float* bh = dir ? bhh_b : bhh_f;
    float bias[4];
#pragma unroll
    for (int j = 0; j < 4; j++) {
        int n = n0 + tx * 4 + j;
        bias[j] = bi[n] + bh[n];
    }
    float* outBase = g_Xp + (size_t)dir * MROWS * GC;
#pragma unroll
    for (int i = 0; i < 8; i++) {
        int r = m0 + ty * 8 + i;
        float4 o;
        o.x = acc[i][0] + bias[0];
        o.y = acc[i][1] + bias[1];
        o.z = acc[i][2] + bias[2];
        o.w = acc[i][3] + bias[3];
        *(float4*)(outBase + (size_t)r * GC + n0 + tx * 4) = o;
    }
}

// =========================================================================
// Kernel 2: persistent bidirectional LSTM. 128 CTAs (<=148 SMs => all
// resident => software grid barrier is safe). CTA owns (dir, 4 hidden
// units) == 16 gate columns. whh slice cached in smem for all 256 steps.
// =========================================================================
#define LSTM_GRID 128

__device__ __forceinline__ void grid_barrier(unsigned target)
{
    __syncthreads();
    if (threadIdx.x == 0) {
        __threadfence();
        unsigned old = atomicAdd(&g_count, 1u);
        if (old == LSTM_GRID - 1) {
            g_count = 0;
            __threadfence();
            atomicAdd(&g_phase, 1u);
        } else {
            while ((int)(*(volatile unsigned*)&g_phase - target) < 0) { }
        }
    }
    __syncthreads();
}

__global__ void __launch_bounds__(256) lstm_kernel(
    const float* __restrict__ whh_f, const float* __restrict__ whh_b,
    const float* __restrict__ h0, const float* __restrict__ c0)
{
    extern __shared__ float smem[];
    // layout: h4 (64*65 float4) | w4 (16*65 float4) | gates (16*65 f) | c (256 f)
    float4* h4   = (float4*)smem;                 // 64 rows x 65 float4 (pad)
    float4* w4   = h4 + 64 * 65;                  // 16 rows x 65 float4 (pad)
    float*  gates = (float*)(w4 + 16 * 65);       // [16][65]
    float*  c_s   = gates + 16 * 65;              // [4][64]

    const int tid = threadIdx.x;
    const int cta = blockIdx.x;
    const int dir = cta >> 6;       // 0 = fwd, 1 = bwd
    const int u0  = (cta & 63) * 4; // first hidden unit owned
    const float* __restrict__ whh = dir ? whh_b : whh_f;

    // load whh slice: 16 gate columns (q*256 + u0+uu), 256 k each
    float* wf = (float*)w4;
    for (int idx = tid; idx < 16 * 256; idx += 256) {
        int ci = idx >> 8, k = idx & 255;
        int q = ci >> 2, uu = ci & 3;
        wf[ci * 260 + k] = whh[(size_t)(q * 256 + u0 + uu) * 256 + k];
    }

    // init h buffer (parity 0) and c (smem-resident, CTA-private)
    {
        int uu = tid >> 6, b = tid & 63;
        int u = u0 + uu;
        g_hbuf[((0 * 2 + dir) * 64 + b) * 256 + u] = h0[(dir * 64 + b) * 256 + u];
        c_s[uu * 64 + b] = c0[(dir * 64 + b) * 256 + u];
    }

    unsigned phase0 = *(volatile unsigned*)&g_phase;
    unsigned barn = 1;
    grid_barrier(phase0 + barn++);   // init h visible everywhere

    const int ci = tid >> 4;    // gate column 0..15
    const int rg = tid & 15;    // row group
    const int q  = ci >> 2, uu = ci & 3;
    const int col = q * 256 + u0 + uu;
    const int uu2 = tid >> 6, b2 = tid & 63;

    int pread = 0;
    for (int st = 0; st < SQ; st++) {
        const int t = dir ? (SQ - 1 - st) : st;

        // stage h (64 x 256 f) into smem, L2-fresh via ldcg
        const float4* hg = (const float4*)(g_hbuf + (size_t)((pread * 2 + dir) * 64) * 256);
        for (int i = tid; i < 64 * 64; i += 256) {
            int b = i >> 6, k4 = i & 63;
            h4[b * 65 + k4] = __ldcg(hg + b * 64 + k4);
        }
        __syncthreads();

        // gate dot products: 16 cols x 64 rows, thread does 4 rows of 1 col
        float accv[4] = {0.f, 0.f, 0.f, 0.f};
        const float4* wrow = w4 + ci * 65;
#pragma unroll 8
        for (int k4 = 0; k4 < 64; k4++) {
            float4 w = wrow[k4];
#pragma unroll
            for (int j = 0; j < 4; j++) {
                float4 h = h4[(rg + 16 * j) * 65 + k4];
                accv[j] += w.x * h.x + w.y * h.y + w.z * h.z + w.w * h.w;
            }
        }
        const float* xrow = g_Xp + (size_t)dir * MROWS * GC + (size_t)t * BB * GC;
#pragma unroll
        for (int j = 0; j < 4; j++) {
            int b = rg + 16 * j;
            gates[ci * 65 + b] = accv[j] + __ldg(xrow + (size_t)b * GC + col);
        }
        __syncthreads();

        // nonlinearity: thread -> (unit uu2, batch b2)
        {
            float gi = gates[(0 * 4 + uu2) * 65 + b2];
            float gf = gates[(1 * 4 + uu2) * 65 + b2];
            float gg = gates[(2 * 4 + uu2) * 65 + b2];
            float go = gates[(3 * 4 + uu2) * 65 + b2];
            float cp = c_s[uu2 * 64 + b2];
            float si = 1.f / (1.f + expf(-gi));
            float sf = 1.f / (1.f + expf(-gf));
            float so = 1.f / (1.f + expf(-go));
            float cn = sf * cp + si * tanhf(gg);
            float hn = so * tanhf(cn);
            c_s[uu2 * 64 + b2] = cn;
            int u = u0 + uu2;
            __stcg(g_hbuf + (size_t)(((pread ^ 1) * 2 + dir) * 64 + b2) * 256 + u, hn);
            g_hs[((size_t)t * 64 + b2) * 512 + dir * 256 + u] = hn;
        }

        if (st != SQ - 1) grid_barrier(phase0 + barn++);
        pread ^= 1;
    }
}

// =========================================================================
// Kernel 3: feats = lstm_out(view B,S,H) @ W_out^T + b_out
//   flat row q = b*S + s reads g_hs flat (the torch "view" trick)
// =========================================================================
__global__ void __launch_bounds__(256) feats_kernel(
    const float* __restrict__ Wout, const float* __restrict__ bout)
{
    int idx = blockIdx.x * blockDim.x + threadIdx.x;   // 163840
    int t = idx % NT;
    int q = idx / NT;
    const float4* h4 = (const float4*)(g_hs + (size_t)q * NH);
    const float4* w4 = (const float4*)(Wout + (size_t)t * NH);
    float acc = 0.f;
#pragma unroll 8
    for (int k = 0; k < NH / 4; k++) {
        float4 a = h4[k], w = w4[k];
        acc += a.x * w.x + a.y * w.y + a.z * w.z + a.w * w.w;
    }
    g_feats[q * NT + t] = acc + bout[t];
}

// =========================================================================
// Kernel 4: Viterbi (single block). first-index-wins argmax == jnp.argmax
// =========================================================================
__global__ void __launch_bounds__(640) viterbi_kernel(
    const float* __restrict__ trans, float* __restrict__ out)
{
    __shared__ float fv[64][11];
    __shared__ float nv[64][11];
    __shared__ float tr[10][10];
    const int tid = threadIdx.x;
    const int b = tid / 10, nx = tid % 10;

    if (tid < 100) tr[tid / 10][tid % 10] = trans[tid];
    fv[b][nx] = (nx == START_TAG) ? 0.f : -10000.f;
    __syncthreads();

    for (int s = 0; s < SQ; s++) {
        float best = -3.0e38f;
        int arg = 0;
#pragma unroll
        for (int p = 0; p < 10; p++) {
            float v = fv[b][p] + tr[nx][p];
            if (v > best) { best = v; arg = p; }
        }
        g_bps[(s * 64 + b) * 10 + nx] = (unsigned char)arg;
        nv[b][nx] = best + g_feats[(b * SQ + s) * NT + nx];
        __syncthreads();
        fv[b][nx] = nv[b][nx];
        __syncthreads();
    }

    if (tid < 64) {
        int bb = tid;
        float best = -3.0e38f;
        int arg = 0;
#pragma unroll
        for (int t = 0; t < 10; t++) {
            float v = fv[bb][t] + tr[STOP_TAG][t];
            if (v > best) { best = v; arg = t; }
        }
        out[bb] = best;                               // path_score (B,1)
        int cur = arg;
        out[64 + bb * SQ + (SQ - 1)] = (float)cur;    // path (B,S)
        for (int s = SQ - 1; s >= 1; s--) {
            cur = g_bps[(s * 64 + bb) * 10 + cur];
            out[64 + bb * SQ + (s - 1)] = (float)cur;
        }
    }
}

// =========================================================================
// launch
// =========================================================================
#define LSTM_SMEM (64 * 65 * 16 + 16 * 65 * 16 + 16 * 65 * 4 + 256 * 4)

extern "C" void kernel_launch(void* const* d_in, const int* in_sizes, int n_in,
                              void* d_out, int out_size)
{
    const int*   sent  = (const int*)d_in[0];
    const float* emb   = (const float*)d_in[1];
    const float* wih_f = (const float*)d_in[2];
    const float* whh_f = (const float*)d_in[3];
    const float* bih_f = (const float*)d_in[4];
    const float* bhh_f = (const float*)d_in[5];
    const float* wih_b = (const float*)d_in[6];
    const float* whh_b = (const float*)d_in[7];
    const float* bih_b = (const float*)d_in[8];
    const float* bhh_b = (const float*)d_in[9];
    const float* Wout  = (const float*)d_in[10];
    const float* bout  = (const float*)d_in[11];

    // transitions (100 elems) may sit at index 12, 13 or 14 depending on
    // whether metadata follows reference-signature or setup_inputs order.
    const float *trans, *h0, *c0;
    if (in_sizes[12] == 100)      { trans = (const float*)d_in[12]; h0 = (const float*)d_in[13]; c0 = (const float*)d_in[14]; }
    else if (in_sizes[14] == 100) { h0 = (const float*)d_in[12]; c0 = (const float*)d_in[13]; trans = (const float*)d_in[14]; }
    else                          { h0 = (const float*)d_in[12]; trans = (const float*)d_in[13]; c0 = (const float*)d_in[14]; }

    cudaFuncSetAttribute(lstm_kernel, cudaFuncAttributeMaxDynamicSharedMemorySize, LSTM_SMEM);

    proj_gemm<<<dim3(32, 128), 256>>>(sent, emb, wih_f, wih_b, bih_f, bhh_f, bih_b, bhh_b);
    lstm_kernel<<<LSTM_GRID, 256, LSTM_SMEM>>>(whh_f, whh_b, h0, c0);
    feats_kernel<<<640, 256>>>(Wout, bout);
    viterbi_kernel<<<1, 640>>>(trans, (float*)d_out);
}

// round 4
// speedup vs baseline: 1.1961x; 1.1961x over previous
#include <cuda_runtime.h>
#include <math.h>
#include <stdint.h>

#define SQ   256
#define BB   64
#define EE   300
#define NH2  256
#define NH   512
#define NT   10
#define GC   1024
#define MROWS 16384
#define START_TAG 8
#define STOP_TAG  9

typedef unsigned long long ull;

// ---------------- device scratch ----------------
__device__ float g_Xp[2ull * 16384ull * 1024ull];   // [dir][r=s*64+b][g]
__device__ float g_hs[16384ull * 512ull];           // [t][h=dir*256+u][b]  (phys rows t*64+b == torch-view flat row)
__device__ float g_hbuf[2 * 2 * 256 * 64];          // [parity][dir][u][b]
__device__ float g_feats[16384 * 10];               // [b*S+s][t]
__device__ unsigned g_cnt[2] = {0, 0};
__device__ unsigned g_ph[2]  = {0, 0};

// ---------------- f32x2 helpers ----------------
__device__ __forceinline__ void fma2(ull& d, ull a, ull b) {
    asm("fma.rn.f32x2 %0, %1, %2, %0;" : "+l"(d) : "l"(a), "l"(b));
}
__device__ __forceinline__ ull pack2(float x, float y) {
    ull r; asm("mov.b64 %0, {%1, %2};" : "=l"(r) : "f"(x), "f"(y)); return r;
}
__device__ __forceinline__ void unpack2(ull v, float& x, float& y) {
    asm("mov.b64 {%0, %1}, %2;" : "=f"(x), "=f"(y) : "l"(v));
}

// =========================================================================
// Kernel 1: embedding gather + input projection GEMM, 128x128 tile, FFMA2
// =========================================================================
__global__ void __launch_bounds__(256) proj_gemm(
    const int* __restrict__ sent, const float* __restrict__ emb,
    const float* __restrict__ wih_f, const float* __restrict__ wih_b,
    const float* __restrict__ bih_f, const float* __restrict__ bhh_f,
    const float* __restrict__ bih_b, const float* __restrict__ bhh_b)
{
    __shared__ __align__(16) float As[16][132];
    __shared__ __align__(16) float Bs[16][132];

    const int tid = threadIdx.x;
    const int m0  = blockIdx.y * 128;
    const int ng0 = blockIdx.x * 128;
    const int dir = (ng0 >= GC) ? 1 : 0;
    const int n0  = ng0 - dir * GC;
    const float* __restrict__ W = dir ? wih_b : wih_f;

    const int lrow = tid & 127;
    const int lk0  = (tid >> 7) * 8;
    const int tok  = sent[m0 + lrow];
    const float* __restrict__ embrow = emb + (size_t)tok * EE;
    const float* __restrict__ wrow   = W + (size_t)(n0 + lrow) * EE;

    const int tx = tid & 15, ty = tid >> 4;

    ull acc2[4][8];
#pragma unroll
    for (int p = 0; p < 4; p++)
#pragma unroll
        for (int j = 0; j < 8; j++) acc2[p][j] = 0ull;

    for (int k0 = 0; k0 < 304; k0 += 16) {
#pragma unroll
        for (int i = 0; i < 8; i++) {
            int k = k0 + lk0 + i;
            As[lk0 + i][lrow] = (k < EE) ? embrow[k] : 0.f;
            Bs[lk0 + i][lrow] = (k < EE) ? wrow[k] : 0.f;
        }
        __syncthreads();
#pragma unroll
        for (int k = 0; k < 16; k++) {
            ulonglong2 A0 = *(const ulonglong2*)&As[k][ty * 4];
            ulonglong2 A1 = *(const ulonglong2*)&As[k][64 + ty * 4];
            float4 b0 = *(const float4*)&Bs[k][tx * 4];
            float4 b1 = *(const float4*)&Bs[k][64 + tx * 4];
            ull bb[8];
            bb[0] = pack2(b0.x, b0.x); bb[1] = pack2(b0.y, b0.y);
            bb[2] = pack2(b0.z, b0.z); bb[3] = pack2(b0.w, b0.w);
            bb[4] = pack2(b1.x, b1.x); bb[5] = pack2(b1.y, b1.y);
            bb[6] = pack2(b1.z, b1.z); bb[7] = pack2(b1.w, b1.w);
#pragma unroll
            for (int j = 0; j < 8; j++) {
                fma2(acc2[0][j], A0.x, bb[j]);
                fma2(acc2[1][j], A0.y, bb[j]);
                fma2(acc2[2][j], A1.x, bb[j]);
                fma2(acc2[3][j], A1.y, bb[j]);
            }
        }
        __syncthreads();
    }

    const float* bi = dir ? bih_b : bih_f;
    const float* bh = dir ? bhh_b : bhh_f;
    float bias[8];
#pragma unroll
    for (int j = 0; j < 8; j++) {
        int n = n0 + ((j < 4) ? (tx * 4 + j) : (64 + tx * 4 + j - 4));
        bias[j] = bi[n] + bh[n];
    }
    float* ob = g_Xp + (size_t)dir * MROWS * GC;
#pragma unroll
    for (int p = 0; p < 4; p++) {
        int r0 = m0 + (p >> 1) * 64 + ty * 4 + (p & 1) * 2;
        float lo[8], hi[8];
#pragma unroll
        for (int j = 0; j < 8; j++) unpack2(acc2[p][j], lo[j], hi[j]);
        float4 o;
        o.x = lo[0] + bias[0]; o.y = lo[1] + bias[1]; o.z = lo[2] + bias[2]; o.w = lo[3] + bias[3];
        *(float4*)(ob + (size_t)r0 * GC + n0 + tx * 4) = o;
        o.x = lo[4] + bias[4]; o.y = lo[5] + bias[5]; o.z = lo[6] + bias[6]; o.w = lo[7] + bias[7];
        *(float4*)(ob + (size_t)r0 * GC + n0 + 64 + tx * 4) = o;
        o.x = hi[0] + bias[0]; o.y = hi[1] + bias[1]; o.z = hi[2] + bias[2]; o.w = hi[3] + bias[3];
        *(float4*)(ob + (size_t)(r0 + 1) * GC + n0 + tx * 4) = o;
        o.x = hi[4] + bias[4]; o.y = hi[5] + bias[5]; o.z = hi[6] + bias[6]; o.w = hi[7] + bias[7];
        *(float4*)(ob + (size_t)(r0 + 1) * GC + n0 + 64 + tx * 4) = o;
    }
}

// =========================================================================
// Kernel 2: persistent BiLSTM, FFMA2, transposed h, per-direction barriers
// =========================================================================
__device__ __forceinline__ void dir_barrier(int dir, unsigned target)
{
    __syncthreads();
    if (threadIdx.x == 0) {
        __threadfence();
        unsigned old = atomicAdd(&g_cnt[dir], 1u);
        if (old == 63u) {
            g_cnt[dir] = 0;
            __threadfence();
            atomicAdd(&g_ph[dir], 1u);
        } else {
            while ((int)(*(volatile unsigned*)&g_ph[dir] - target) < 0) { }
        }
    }
    __syncthreads();
}

// dynamic smem: h_s 16384f | w_s 16*258f | gates 16*72f | c_s 256f
#define LSTM_SMEM ((16384 + 16*258 + 16*72 + 256) * 4)

__global__ void __launch_bounds__(256) lstm_kernel(
    const float* __restrict__ whh_f, const float* __restrict__ whh_b,
    const float* __restrict__ h0, const float* __restrict__ c0)
{
    extern __shared__ __align__(16) float smem[];
    float* h_s   = smem;                 // [k=256][b=64]
    float* w_s   = h_s + 16384;          // [ci=16][k=256] stride 258
    float* gates = w_s + 16 * 258;       // [ci=16][b] stride 72
    float* c_s   = gates + 16 * 72;      // [uu=4][b=64]

    const int tid = threadIdx.x;
    const int cta = blockIdx.x;
    const int dir = cta >> 6;
    const int u0  = (cta & 63) * 4;
    const float* __restrict__ whh = dir ? whh_b : whh_f;

    // load whh slice: w_s[ci][k] = whh[(q*256 + u0+uu)][k], ci = q*4+uu
    for (int idx = tid; idx < 16 * 256; idx += 256) {
        int ci = idx >> 8, k = idx & 255;
        w_s[ci * 258 + k] = whh[(size_t)((ci >> 2) * 256 + u0 + (ci & 3)) * 256 + k];
    }

    const int uu2 = tid >> 6, b2 = tid & 63;
    const int u = u0 + uu2;
    g_hbuf[(0 * 2 + dir) * 16384 + u * 64 + b2] = h0[(dir * 64 + b2) * 256 + u];
    c_s[uu2 * 64 + b2] = c0[(dir * 64 + b2) * 256 + u];

    unsigned ph0 = *(volatile unsigned*)&g_ph[dir];
    unsigned bn = 1;
    dir_barrier(dir, ph0 + bn); bn++;

    const int ci = tid >> 4, rg = tid & 15;
    const int col = (ci >> 2) * 256 + u0 + (ci & 3);

    int pread = 0;
    for (int st = 0; st < SQ; st++) {
        const int t = dir ? (SQ - 1 - st) : st;

        // prefetch Xp for this step (overlaps with h staging)
        float xv[4];
        const float* xp = g_Xp + (size_t)dir * MROWS * GC + (size_t)t * BB * GC;
#pragma unroll
        for (int j = 0; j < 4; j++)
            xv[j] = __ldg(xp + (size_t)(rg * 4 + j) * GC + col);

        // stage h [k][b] into smem (L2-fresh)
        {
            const float4* hg = (const float4*)(g_hbuf + (size_t)(pread * 2 + dir) * 16384);
            float4* hd = (float4*)h_s;
#pragma unroll
            for (int i = 0; i < 16; i++)
                hd[tid + 256 * i] = __ldcg(hg + tid + 256 * i);
        }
        __syncthreads();

        // FFMA2 gate dot products: col ci, rows rg*4..rg*4+3 (2 packed accs)
        ull acc0 = 0ull, acc1 = 0ull;
        const float* wp = w_s + ci * 258;
        const float* hp = h_s + rg * 4;
#pragma unroll 16
        for (int k = 0; k < 256; k += 2) {
            float2 w2 = *(const float2*)(wp + k);
            ulonglong2 ha = *(const ulonglong2*)(hp + (size_t)k * 64);
            ulonglong2 hb = *(const ulonglong2*)(hp + (size_t)(k + 1) * 64);
            ull wa = pack2(w2.x, w2.x);
            ull wb = pack2(w2.y, w2.y);
            fma2(acc0, wa, ha.x); fma2(acc1, wa, ha.y);
            fma2(acc0, wb, hb.x); fma2(acc1, wb, hb.y);
        }
        float g0, g1, g2, g3;
        unpack2(acc0, g0, g1); unpack2(acc1, g2, g3);
        gates[ci * 72 + rg * 4 + 0] = g0 + xv[0];
        gates[ci * 72 + rg * 4 + 1] = g1 + xv[1];
        gates[ci * 72 + rg * 4 + 2] = g2 + xv[2];
        gates[ci * 72 + rg * 4 + 3] = g3 + xv[3];
        __syncthreads();

        // nonlinearity: thread -> (unit uu2, batch b2)
        {
            float gi = gates[(0 + uu2) * 72 + b2];
            float gf = gates[(4 + uu2) * 72 + b2];
            float gg = gates[(8 + uu2) * 72 + b2];
            float go = gates[(12 + uu2) * 72 + b2];
            float cp = c_s[uu2 * 64 + b2];
            float si = 1.f / (1.f + expf(-gi));
            float sf = 1.f / (1.f + expf(-gf));
            float so = 1.f / (1.f + expf(-go));
            float cn = sf * cp + si * tanhf(gg);
            float hn = so * tanhf(cn);
            c_s[uu2 * 64 + b2] = cn;
            __stcg(g_hbuf + (size_t)((pread ^ 1) * 2 + dir) * 16384 + u * 64 + b2, hn);
            g_hs[((size_t)t * 512 + dir * 256 + u) * 64 + b2] = hn;   // coalesced
        }

        if (st != SQ - 1) { dir_barrier(dir, ph0 + bn); bn++; }
        pread ^= 1;
    }
}

// =========================================================================
// Kernel 3: feats. hs phys row r = t*64+b corresponds to torch-view flat
// row q = r. out[q][t] = sum_h hs[t_phys][h][b_phys] * W[t][h] + b[t]
// =========================================================================
__global__ void __launch_bounds__(64) feats_kernel(
    const float* __restrict__ Wout, const float* __restrict__ bout)
{
    __shared__ __align__(8) float Ws[512 * 10 + 2];   // [h][t]
    __shared__ float bs[10];
    const int tid = threadIdx.x;
    const int ts  = blockIdx.x;     // physical timestep
    const int b   = tid;            // physical batch

    for (int i = tid; i < 5120; i += 64) {
        int h = i / 10, t = i - h * 10;
        Ws[i] = Wout[(size_t)t * NH + h];
    }
    if (tid < 10) bs[tid] = bout[tid];
    __syncthreads();

    ull acc[5] = {0ull, 0ull, 0ull, 0ull, 0ull};
    const float* hp = g_hs + (size_t)ts * 512 * 64 + b;
#pragma unroll 4
    for (int h = 0; h < 512; h++) {
        float v = __ldg(hp + (size_t)h * 64);
        ull vv = pack2(v, v);
        const ull* wr = (const ull*)&Ws[h * 10];
        fma2(acc[0], vv, wr[0]);
        fma2(acc[1], vv, wr[1]);
        fma2(acc[2], vv, wr[2]);
        fma2(acc[3], vv, wr[3]);
        fma2(acc[4], vv, wr[4]);
    }
    float* out = g_feats + (size_t)(ts * 64 + b) * NT;
#pragma unroll
    for (int j = 0; j < 5; j++) {
        float x, y;
        unpack2(acc[j], x, y);
        out[2 * j]     = x + bs[2 * j];
        out[2 * j + 1] = y + bs[2 * j + 1];
    }
}

// =========================================================================
// Kernel 4: Viterbi. Backpointers in smem, feats prefetch, 1 sync/step.
// =========================================================================
#define VIT_SMEM (256 * 64 * 10)

__global__ void __launch_bounds__(640) viterbi_kernel(
    const float* __restrict__ trans, float* __restrict__ out)
{
    extern __shared__ unsigned char bps[];            // [s][b][nx]
    __shared__ float fv[2][64][12];
    const int tid = threadIdx.x;
    const int b = tid / 10, nx = tid - b * 10;

    float trr[10];
#pragma unroll
    for (int p = 0; p < 10; p++) trr[p] = trans[nx * 10 + p];

    fv[0][b][nx] = (nx == START_TAG) ? 0.f : -10000.f;
    __syncthreads();

    const float* frow = g_feats + (size_t)b * SQ * NT + nx;
    float fnext = __ldg(frow);
    int p = 0;
    for (int s = 0; s < SQ; s++) {
        float fcur = fnext;
        if (s < SQ - 1) fnext = __ldg(frow + (s + 1) * NT);
        float best = -3.0e38f;
        int arg = 0;
#pragma unroll
        for (int pp = 0; pp < 10; pp++) {
            float v = fv[p][b][pp] + trr[pp];
            if (v > best) { best = v; arg = pp; }
        }
        bps[(s * 64 + b) * 10 + nx] = (unsigned char)arg;
        fv[p ^ 1][b][nx] = best + fcur;
        __syncthreads();
        p ^= 1;
    }

    if (tid < 64) {
        const int bb = tid;
        float best = -3.0e38f;
        int arg = 0;
#pragma unroll
        for (int t = 0; t < 10; t++) {
            float v = fv[p][bb][t] + trans[STOP_TAG * 10 + t];
            if (v > best) { best = v; arg = t; }
        }
        out[bb] = best;
        int cur = arg;
        out[64 + bb * SQ + (SQ - 1)] = (float)cur;
        for (int s = SQ - 1; s >= 1; s--) {
            cur = bps[(s * 64 + bb) * 10 + cur];
            out[64 + bb * SQ + (s - 1)] = (float)cur;
        }
    }
}

// =========================================================================
// launch
// =========================================================================
extern "C" void kernel_launch(void* const* d_in, const int* in_sizes, int n_in,
                              void* d_out, int out_size)
{
    const int*   sent  = (const int*)d_in[0];
    const float* emb   = (const float*)d_in[1];
    const float* wih_f = (const float*)d_in[2];
    const float* whh_f = (const float*)d_in[3];
    const float* bih_f = (const float*)d_in[4];
    const float* bhh_f = (const float*)d_in[5];
    const float* wih_b = (const float*)d_in[6];
    const float* whh_b = (const float*)d_in[7];
    const float* bih_b = (const float*)d_in[8];
    const float* bhh_b = (const float*)d_in[9];
    const float* Wout  = (const float*)d_in[10];
    const float* bout  = (const float*)d_in[11];

    const float *trans, *h0, *c0;
    if (in_sizes[12] == 100)      { trans = (const float*)d_in[12]; h0 = (const float*)d_in[13]; c0 = (const float*)d_in[14]; }
    else if (in_sizes[14] == 100) { h0 = (const float*)d_in[12]; c0 = (const float*)d_in[13]; trans = (const float*)d_in[14]; }
    else                          { h0 = (const float*)d_in[12]; trans = (const float*)d_in[13]; c0 = (const float*)d_in[14]; }

    cudaFuncSetAttribute(lstm_kernel, cudaFuncAttributeMaxDynamicSharedMemorySize, LSTM_SMEM);
    cudaFuncSetAttribute(viterbi_kernel, cudaFuncAttributeMaxDynamicSharedMemorySize, VIT_SMEM);

    proj_gemm<<<dim3(16, 128), 256>>>(sent, emb, wih_f, wih_b, bih_f, bhh_f, bih_b, bhh_b);
    lstm_kernel<<<128, 256, LSTM_SMEM>>>(whh_f, whh_b, h0, c0);
    feats_kernel<<<256, 64>>>(Wout, bout);
    viterbi_kernel<<<1, 640, VIT_SMEM>>>(trans, (float*)d_out);
}

// round 6
// speedup vs baseline: 1.4188x; 1.1861x over previous
#include <cuda_runtime.h>
#include <math.h>
#include <stdint.h>

#define SQ   256
#define BB   64
#define EE   300
#define NH2  256
#define NH   512
#define NT   10
#define GC   1024
#define MROWS 16384
#define START_TAG 8
#define STOP_TAG  9

typedef unsigned long long ull;

// ---------------- device scratch ----------------
__device__ float g_Xp[2ull * 16384ull * 1024ull];   // [dir][r=s*64+b][g]
__device__ float g_hs[16384ull * 512ull];           // [t][h=dir*256+u][b]
__device__ float g_hbuf[2 * 2 * 256 * 64];          // [parity][dir][u][b]
__device__ float g_feats[16384 * 10];               // [b*S+s][t]
__device__ unsigned g_cnt[2] = {0, 0};
__device__ unsigned g_ph[2]  = {0, 0};

// ---------------- f32x2 helpers ----------------
__device__ __forceinline__ void fma2(ull& d, ull a, ull b) {
    asm("fma.rn.f32x2 %0, %1, %2, %0;" : "+l"(d) : "l"(a), "l"(b));
}
__device__ __forceinline__ void add2(ull& d, ull a) {
    asm("add.rn.f32x2 %0, %0, %1;" : "+l"(d) : "l"(a));
}
__device__ __forceinline__ ull pack2(float x, float y) {
    ull r; asm("mov.b64 %0, {%1, %2};" : "=l"(r) : "f"(x), "f"(y)); return r;
}
__device__ __forceinline__ void unpack2(ull v, float& x, float& y) {
    asm("mov.b64 {%0, %1}, %2;" : "=f"(x), "=f"(y) : "l"(v));
}

// =========================================================================
// Kernel 1: embedding gather + input projection GEMM, 128x128 tile, FFMA2
// =========================================================================
__global__ void __launch_bounds__(256) proj_gemm(
    const int* __restrict__ sent, const float* __restrict__ emb,
    const float* __restrict__ wih_f, const float* __restrict__ wih_b,
    const float* __restrict__ bih_f, const float* __restrict__ bhh_f,
    const float* __restrict__ bih_b, const float* __restrict__ bhh_b)
{
    __shared__ __align__(16) float As[16][132];
    __shared__ __align__(16) float Bs[16][132];

    const int tid = threadIdx.x;
    const int m0  = blockIdx.y * 128;
    const int ng0 = blockIdx.x * 128;
    const int dir = (ng0 >= GC) ? 1 : 0;
    const int n0  = ng0 - dir * GC;
    const float* __restrict__ W = dir ? wih_b : wih_f;

    const int lrow = tid & 127;
    const int lk0  = (tid >> 7) * 8;
    const int tok  = sent[m0 + lrow];
    const float* __restrict__ embrow = emb + (size_t)tok * EE;
    const float* __restrict__ wrow   = W + (size_t)(n0 + lrow) * EE;

    const int tx = tid & 15, ty = tid >> 4;

    ull acc2[4][8];
#pragma unroll
    for (int p = 0; p < 4; p++)
#pragma unroll
        for (int j = 0; j < 8; j++) acc2[p][j] = 0ull;

    for (int k0 = 0; k0 < 304; k0 += 16) {
#pragma unroll
        for (int i = 0; i < 8; i++) {
            int k = k0 + lk0 + i;
            As[lk0 + i][lrow] = (k < EE) ? embrow[k] : 0.f;
            Bs[lk0 + i][lrow] = (k < EE) ? wrow[k] : 0.f;
        }
        __syncthreads();
#pragma unroll
        for (int k = 0; k < 16; k++) {
            ulonglong2 A0 = *(const ulonglong2*)&As[k][ty * 4];
            ulonglong2 A1 = *(const ulonglong2*)&As[k][64 + ty * 4];
            float4 b0 = *(const float4*)&Bs[k][tx * 4];
            float4 b1 = *(const float4*)&Bs[k][64 + tx * 4];
            ull bb[8];
            bb[0] = pack2(b0.x, b0.x); bb[1] = pack2(b0.y, b0.y);
            bb[2] = pack2(b0.z, b0.z); bb[3] = pack2(b0.w, b0.w);
            bb[4] = pack2(b1.x, b1.x); bb[5] = pack2(b1.y, b1.y);
            bb[6] = pack2(b1.z, b1.z); bb[7] = pack2(b1.w, b1.w);
#pragma unroll
            for (int j = 0; j < 8; j++) {
                fma2(acc2[0][j], A0.x, bb[j]);
                fma2(acc2[1][j], A0.y, bb[j]);
                fma2(acc2[2][j], A1.x, bb[j]);
                fma2(acc2[3][j], A1.y, bb[j]);
            }
        }
        __syncthreads();
    }

    const float* bi = dir ? bih_b : bih_f;
    const float* bh = dir ? bhh_b : bhh_f;
    float bias[8];
#pragma unroll
    for (int j = 0; j < 8; j++) {
        int n = n0 + ((j < 4) ? (tx * 4 + j) : (64 + tx * 4 + j - 4));
        bias[j] = bi[n] + bh[n];
    }
    float* ob = g_Xp + (size_t)dir * MROWS * GC;
#pragma unroll
    for (int p = 0; p < 4; p++) {
        int r0 = m0 + (p >> 1) * 64 + ty * 4 + (p & 1) * 2;
        float lo[8], hi[8];
#pragma unroll
        for (int j = 0; j < 8; j++) unpack2(acc2[p][j], lo[j], hi[j]);
        float4 o;
        o.x = lo[0] + bias[0]; o.y = lo[1] + bias[1]; o.z = lo[2] + bias[2]; o.w = lo[3] + bias[3];
        *(float4*)(ob + (size_t)r0 * GC + n0 + tx * 4) = o;
        o.x = lo[4] + bias[4]; o.y = lo[5] + bias[5]; o.z = lo[6] + bias[6]; o.w = lo[7] + bias[7];
        *(float4*)(ob + (size_t)r0 * GC + n0 + 64 + tx * 4) = o;
        o.x = hi[0] + bias[0]; o.y = hi[1] + bias[1]; o.z = hi[2] + bias[2]; o.w = hi[3] + bias[3];
        *(float4*)(ob + (size_t)(r0 + 1) * GC + n0 + tx * 4) = o;
        o.x = hi[4] + bias[4]; o.y = hi[5] + bias[5]; o.z = hi[6] + bias[6]; o.w = hi[7] + bias[7];
        *(float4*)(ob + (size_t)(r0 + 1) * GC + n0 + 64 + tx * 4) = o;
    }
}

// =========================================================================
// Kernel 2: persistent BiLSTM. Warps split K (no duplicated h reads),
// w-operands broadcast from smem as packed f32x2, 8-way smem reduction
// fused with the nonlinearity epilogue.
// =========================================================================
__device__ __forceinline__ void dir_barrier(int dir, unsigned target)
{
    __syncthreads();
    if (threadIdx.x == 0) {
        __threadfence();
        unsigned old = atomicAdd(&g_cnt[dir], 1u);
        if (old == 63u) {
            g_cnt[dir] = 0;
            __threadfence();
            atomicAdd(&g_ph[dir], 1u);
        } else {
            while ((int)(*(volatile unsigned*)&g_ph[dir] - target) < 0) { }
        }
    }
    __syncthreads();
}

// dynamic smem: h_s 16384f | wp_s 4096 ull | red 4096 ull | xp_s 1024f | c_s 256f
#define LSTM_SMEM (16384*4 + 4096*8 + 4096*8 + 1024*4 + 256*4)

__global__ void __launch_bounds__(256) lstm_kernel(
    const float* __restrict__ whh_f, const float* __restrict__ whh_b,
    const float* __restrict__ h0, const float* __restrict__ c0)
{
    extern __shared__ __align__(16) float smem[];
    float* h_s  = smem;                    // [k=256][b=64]
    ull*   wp_s = (ull*)(h_s + 16384);     // [k=256][ci=16] packed (w,w)
    ull*   red  = wp_s + 4096;             // [ci=16][w=8][l=32]
    float* xp_s = (float*)(red + 4096);    // [ci=16][b=64]
    float* c_s  = xp_s + 1024;             // [uu=4][b=64]

    const int tid = threadIdx.x;
    const int cta = blockIdx.x;
    const int dir = cta >> 6;
    const int u0  = (cta & 63) * 4;
    const float* __restrict__ whh = dir ? whh_b : whh_f;

    // build packed whh slice: wp_s[k][ci] = (w,w), ci = q*4+uu, col = q*256+u0+uu
    for (int idx = tid; idx < 4096; idx += 256) {
        int ci = idx >> 8, k = idx & 255;
        float v = whh[(size_t)((ci >> 2) * 256 + u0 + (ci & 3)) * 256 + k];
        wp_s[k * 16 + ci] = pack2(v, v);
    }

    // init hbuf (parity 0) and c
    {
        int uu = tid >> 6, b = tid & 63;
        int u = u0 + uu;
        g_hbuf[(0 * 2 + dir) * 16384 + u * 64 + b] = h0[(dir * 64 + b) * 256 + u];
        c_s[uu * 64 + b] = c0[(dir * 64 + b) * 256 + u];
    }

    unsigned ph0 = *(volatile unsigned*)&g_ph[dir];
    unsigned bn = 1;
    dir_barrier(dir, ph0 + bn); bn++;

    const int wrp = tid >> 5, ln = tid & 31;
    const float* XpD = g_Xp + (size_t)dir * MROWS * GC;

    int pread = 0;
    for (int st = 0; st < SQ; st++) {
        const int t = dir ? (SQ - 1 - st) : st;

        // gather Xp tile for this step into smem (one float4 per thread)
        {
            int b = tid & 63, q = tid >> 6;
            float4 v = *(const float4*)(XpD + ((size_t)t * 64 + b) * GC + q * 256 + u0);
            xp_s[(q * 4 + 0) * 64 + b] = v.x;
            xp_s[(q * 4 + 1) * 64 + b] = v.y;
            xp_s[(q * 4 + 2) * 64 + b] = v.z;
            xp_s[(q * 4 + 3) * 64 + b] = v.w;
        }
        // stage h [k][b] into smem (L2-fresh)
        {
            const float4* hg = (const float4*)(g_hbuf + (size_t)(pread * 2 + dir) * 16384);
            float4* hd = (float4*)h_s;
#pragma unroll
            for (int i = 0; i < 16; i++)
                hd[tid + 256 * i] = __ldcg(hg + tid + 256 * i);
        }
        __syncthreads();

        // partial gate GEMM: warp wrp does k in [wrp*32, wrp*32+32),
        // all 16 cols, lane ln = batch pair (2ln, 2ln+1)
        {
            ull acc[16];
#pragma unroll
            for (int ci = 0; ci < 16; ci++) acc[ci] = 0ull;
            const ull* hp = (const ull*)h_s + (size_t)wrp * 32 * 32 + ln;
            const ull* wq = wp_s + wrp * 32 * 16;
#pragma unroll 4
            for (int kk = 0; kk < 32; kk++) {
                ull h2 = hp[kk * 32];
                const ulonglong2* wv = (const ulonglong2*)(wq + kk * 16);
#pragma unroll
                for (int j = 0; j < 8; j++) {
                    ulonglong2 wj = wv[j];
                    fma2(acc[2 * j],     wj.x, h2);
                    fma2(acc[2 * j + 1], wj.y, h2);
                }
            }
#pragma unroll
            for (int ci = 0; ci < 16; ci++)
                red[(ci * 8 + wrp) * 32 + ln] = acc[ci];
        }
        __syncthreads();

        // epilogue (128 threads): reduce 8 partials, add Xp, nonlinearity
        if (tid < 128) {
            int uu = tid >> 5, l = tid & 31;
            ull s[4];
#pragma unroll
            for (int q = 0; q < 4; q++) {
                int ci = q * 4 + uu;
                const ull* rp = red + ci * 256 + l;
                ull a = rp[0];
#pragma unroll
                for (int w = 1; w < 8; w++) add2(a, rp[w * 32]);
                float2 xv = *(const float2*)(xp_s + ci * 64 + 2 * l);
                add2(a, pack2(xv.x, xv.y));
                s[q] = a;
            }
            float gi0, gi1, gf0, gf1, gg0, gg1, go0, go1;
            unpack2(s[0], gi0, gi1); unpack2(s[1], gf0, gf1);
            unpack2(s[2], gg0, gg1); unpack2(s[3], go0, go1);
            float2 cp = *(const float2*)(c_s + uu * 64 + 2 * l);

            float si0 = 1.f / (1.f + expf(-gi0));
            float sf0 = 1.f / (1.f + expf(-gf0));
            float so0 = 1.f / (1.f + expf(-go0));
            float cn0 = sf0 * cp.x + si0 * tanhf(gg0);
            float hn0 = so0 * tanhf(cn0);

            float si1 = 1.f / (1.f + expf(-gi1));
            float sf1 = 1.f / (1.f + expf(-gf1));
            float so1 = 1.f / (1.f + expf(-go1));
            float cn1 = sf1 * cp.y + si1 * tanhf(gg1);
            float hn1 = so1 * tanhf(cn1);

            *(float2*)(c_s + uu * 64 + 2 * l) = make_float2(cn0, cn1);
            int u = u0 + uu;
            float2 hv = make_float2(hn0, hn1);
            __stcg((float2*)(g_hbuf + (size_t)((pread ^ 1) * 2 + dir) * 16384 + u * 64 + 2 * l), hv);
            *(float2*)(g_hs + ((size_t)t * 512 + dir * 256 + u) * 64 + 2 * l) = hv;
        }

        if (st != SQ - 1) { dir_barrier(dir, ph0 + bn); bn++; }
        pread ^= 1;
    }
}

// =========================================================================
// Kernel 3: feats
// =========================================================================
__global__ void __launch_bounds__(64) feats_kernel(
    const float* __restrict__ Wout, const float* __restrict__ bout)
{
    __shared__ __align__(8) float Ws[512 * 10 + 2];   // [h][t]
    __shared__ float bs[10];
    const int tid = threadIdx.x;
    const int ts  = blockIdx.x;
    const int b   = tid;

    for (int i = tid; i < 5120; i += 64) {
        int h = i / 10, t = i - h * 10;
        Ws[i] = Wout[(size_t)t * NH + h];
    }
    if (tid < 10) bs[tid] = bout[tid];
    __syncthreads();

    ull acc[5] = {0ull, 0ull, 0ull, 0ull, 0ull};
    const float* hp = g_hs + (size_t)ts * 512 * 64 + b;
#pragma unroll 4
    for (int h = 0; h < 512; h++) {
        float v = __ldg(hp + (size_t)h * 64);
        ull vv = pack2(v, v);
        const ull* wr = (const ull*)&Ws[h * 10];
        fma2(acc[0], vv, wr[0]);
        fma2(acc[1], vv, wr[1]);
        fma2(acc[2], vv, wr[2]);
        fma2(acc[3], vv, wr[3]);
        fma2(acc[4], vv, wr[4]);
    }
    float* out = g_feats + (size_t)(ts * 64 + b) * NT;
#pragma unroll
    for (int j = 0; j < 5; j++) {
        float x, y;
        unpack2(acc[j], x, y);
        out[2 * j]     = x + bs[2 * j];
        out[2 * j + 1] = y + bs[2 * j + 1];
    }
}

// =========================================================================
// Kernel 4: Viterbi
// =========================================================================
#define VIT_SMEM (256 * 64 * 10)

__global__ void __launch_bounds__(640) viterbi_kernel(
    const float* __restrict__ trans, float* __restrict__ out)
{
    extern __shared__ unsigned char bps[];            // [s][b][nx]
    __shared__ float fv[2][64][12];
    const int tid = threadIdx.x;
    const int b = tid / 10, nx = tid - b * 10;

    float trr[10];
#pragma unroll
    for (int p = 0; p < 10; p++) trr[p] = trans[nx * 10 + p];

    fv[0][b][nx] = (nx == START_TAG) ? 0.f : -10000.f;
    __syncthreads();

    const float* frow = g_feats + (size_t)b * SQ * NT + nx;
    float fnext = __ldg(frow);
    int p = 0;
    for (int s = 0; s < SQ; s++) {
        float fcur = fnext;
        if (s < SQ - 1) fnext = __ldg(frow + (s + 1) * NT);
        float best = -3.0e38f;
        int arg = 0;
#pragma unroll
        for (int pp = 0; pp < 10; pp++) {
            float v = fv[p][b][pp] + trr[pp];
            if (v > best) { best = v; arg = pp; }
        }
        bps[(s * 64 + b) * 10 + nx] = (unsigned char)arg;
        fv[p ^ 1][b][nx] = best + fcur;
        __syncthreads();
        p ^= 1;
    }

    if (tid < 64) {
        const int bb = tid;
        float best = -3.0e38f;
        int arg = 0;
#pragma unroll
        for (int t = 0; t < 10; t++) {
            float v = fv[p][bb][t] + trans[STOP_TAG * 10 + t];
            if (v > best) { best = v; arg = t; }
        }
        out[bb] = best;
        int cur = arg;
        out[64 + bb * SQ + (SQ - 1)] = (float)cur;
        for (int s = SQ - 1; s >= 1; s--) {
            cur = bps[(s * 64 + bb) * 10 + cur];
            out[64 + bb * SQ + (s - 1)] = (float)cur;
        }
    }
}

// =========================================================================
// launch
// =========================================================================
extern "C" void kernel_launch(void* const* d_in, const int* in_sizes, int n_in,
                              void* d_out, int out_size)
{
    const int*   sent  = (const int*)d_in[0];
    const float* emb   = (const float*)d_in[1];
    const float* wih_f = (const float*)d_in[2];
    const float* whh_f = (const float*)d_in[3];
    const float* bih_f = (const float*)d_in[4];
    const float* bhh_f = (const float*)d_in[5];
    const float* wih_b = (const float*)d_in[6];
    const float* whh_b = (const float*)d_in[7];
    const float* bih_b = (const float*)d_in[8];
    const float* bhh_b = (const float*)d_in[9];
    const float* Wout  = (const float*)d_in[10];
    const float* bout  = (const float*)d_in[11];

    const float *trans, *h0, *c0;
    if (in_sizes[12] == 100)      { trans = (const float*)d_in[12]; h0 = (const float*)d_in[13]; c0 = (const float*)d_in[14]; }
    else if (in_sizes[14] == 100) { h0 = (const float*)d_in[12]; c0 = (const float*)d_in[13]; trans = (const float*)d_in[14]; }
    else                          { h0 = (const float*)d_in[12]; trans = (const float*)d_in[13]; c0 = (const float*)d_in[14]; }

    cudaFuncSetAttribute(lstm_kernel, cudaFuncAttributeMaxDynamicSharedMemorySize, LSTM_SMEM);
    cudaFuncSetAttribute(viterbi_kernel, cudaFuncAttributeMaxDynamicSharedMemorySize, VIT_SMEM);

    proj_gemm<<<dim3(16, 128), 256>>>(sent, emb, wih_f, wih_b, bih_f, bhh_f, bih_b, bhh_b);
    lstm_kernel<<<128, 256, LSTM_SMEM>>>(whh_f, whh_b, h0, c0);
    feats_kernel<<<256, 64>>>(Wout, bout);
    viterbi_kernel<<<1, 640, VIT_SMEM>>>(trans, (float*)d_out);
}